// round 5
// baseline (speedup 1.0000x reference)
#include <cuda_runtime.h>

#define NB 8
#define NP 4096
#define NS 1024

// ---------------- device scratch (static: no allocation allowed) ----------------
__device__ float gPQ0[NB*NP*32];
__device__ float gPQ1[NB*NP*64];
__device__ float gPQ2[NB*NP*64];
__device__ int   gIdx0[NB*NS*16];
__device__ int   gIdx1[NB*NS*32];
__device__ int   gIdx2[NB*NS*128];

// packed fp32x2 FMA (sm_100+): 2 MACs/instr
__device__ __forceinline__ float2 ffma2(float2 a, float2 b, float2 c){
    unsigned long long au, bu, cu, du;
    au = *reinterpret_cast<const unsigned long long*>(&a);
    bu = *reinterpret_cast<const unsigned long long*>(&b);
    cu = *reinterpret_cast<const unsigned long long*>(&c);
    asm("fma.rn.f32x2 %0, %1, %2, %3;" : "=l"(du) : "l"(au), "l"(bu), "l"(cu));
    return *reinterpret_cast<float2*>(&du);
}
__device__ __forceinline__ float2 f2lo(float4 v){ return make_float2(v.x, v.y); }
__device__ __forceinline__ float2 f2hi(float4 v){ return make_float2(v.z, v.w); }

// ---------------- FPS: 1 CTA/batch, 1024-step sequential chain ----------------
__global__ void __launch_bounds__(1024) fps_kernel(
    const float* __restrict__ xyz, float* __restrict__ newxyz)
{
    __shared__ unsigned long long swarp[32];
    __shared__ float scent[3];
    __shared__ unsigned swidx;
    const int b = blockIdx.x, tid = threadIdx.x;
    const float* xb = xyz + (size_t)b * NP * 3;

    float px[4], py[4], pz[4], dist[4];
#pragma unroll
    for (int i = 0; i < 4; i++){
        int p = tid + 1024*i;
        px[i] = xb[3*p]; py[i] = xb[3*p+1]; pz[i] = xb[3*p+2];
        dist[i] = 1e10f;
    }
    if (tid == 0){ scent[0] = px[0]; scent[1] = py[0]; scent[2] = pz[0]; }
    __syncthreads();

    for (int it = 0; it < NS; ++it){
        float cx = scent[0], cy = scent[1], cz = scent[2];
        if (tid == 0){
            float* o = newxyz + ((size_t)b * NS + it) * 3;
            o[0] = cx; o[1] = cy; o[2] = cz;
        }
        unsigned long long best = 0ull;
#pragma unroll
        for (int i = 0; i < 4; i++){
            float dx = px[i]-cx, dy = py[i]-cy, dz = pz[i]-cz;
            // match XLA: separate-rounded squares, left-to-right reduce
            float d = __fadd_rn(__fadd_rn(__fmul_rn(dx,dx), __fmul_rn(dy,dy)), __fmul_rn(dz,dz));
            float nd = fminf(dist[i], d);
            dist[i] = nd;
            // nd >= 0 so float bits order == value order; ~idx = first-index tie-break
            unsigned long long key = ((unsigned long long)__float_as_uint(nd) << 32)
                                   | (unsigned long long)(0xFFFFFFFFu - (unsigned)(tid + 1024*i));
            if (key > best) best = key;
        }
#pragma unroll
        for (int off = 16; off; off >>= 1){
            unsigned long long o = __shfl_down_sync(0xFFFFFFFFu, best, off);
            if (o > best) best = o;
        }
        if ((tid & 31) == 0) swarp[tid >> 5] = best;
        __syncthreads();
        if (tid < 32){
            unsigned long long v = swarp[tid];
#pragma unroll
            for (int off = 16; off; off >>= 1){
                unsigned long long o = __shfl_down_sync(0xFFFFFFFFu, v, off);
                if (o > v) v = o;
            }
            if (tid == 0) swidx = 0xFFFFFFFFu - (unsigned)(v & 0xFFFFFFFFull);
        }
        __syncthreads();
        unsigned w = swidx;
        if (tid == (w & 1023)){
            int slot = w >> 10;
            scent[0] = (slot==0) ? px[0] : (slot==1) ? px[1] : (slot==2) ? px[2] : px[3];
            scent[1] = (slot==0) ? py[0] : (slot==1) ? py[1] : (slot==2) ? py[2] : py[3];
            scent[2] = (slot==0) ? pz[0] : (slot==1) ? pz[1] : (slot==2) ? pz[2] : pz[3];
        }
        __syncthreads();
    }
}

// ---------------- PQ[n] = W1 @ [xyz_n; feat_n] + b1 (all 3 scales in one kernel) ----------------
__global__ void __launch_bounds__(160) pq_kernel(
    const float* __restrict__ xyz, const float* __restrict__ feat,
    const float* __restrict__ w00, const float* __restrict__ b00,
    const float* __restrict__ w10, const float* __restrict__ b10,
    const float* __restrict__ w20, const float* __restrict__ b20)
{
    __shared__ float sin_[8*68];
    const int tid = threadIdx.x;
    const float* wrow; float bias; float* dst; int C, ch;
    if (tid < 32)      { wrow = w00 + tid*67;      bias = b00[tid];    dst = gPQ0; C = 32; ch = tid; }
    else if (tid < 96) { wrow = w10 + (tid-32)*67; bias = b10[tid-32]; dst = gPQ1; C = 64; ch = tid-32; }
    else               { wrow = w20 + (tid-96)*67; bias = b20[tid-96]; dst = gPQ2; C = 64; ch = tid-96; }
    float wreg[67];
#pragma unroll
    for (int i = 0; i < 67; i++) wreg[i] = wrow[i];

    for (int grp = 0; grp < 4; grp++){
        int gbase = blockIdx.x * 32 + grp * 8;
        __syncthreads();
        for (int t = tid; t < 8*67; t += 160){
            int pt = t / 67, c = t - 67*pt;
            int g = gbase + pt;
            sin_[pt*68 + c] = (c < 3) ? xyz[(size_t)g*3 + c] : feat[(size_t)g*64 + (c-3)];
        }
        __syncthreads();
#pragma unroll 1
        for (int pt = 0; pt < 8; pt++){
            const float* inp = &sin_[pt*68];
            float a0 = bias, a1 = 0.f;
#pragma unroll
            for (int i = 0; i < 8; i++){
                float4 v0 = *reinterpret_cast<const float4*>(inp + 8*i);
                float4 v1 = *reinterpret_cast<const float4*>(inp + 8*i + 4);
                a0 = fmaf(v0.x, wreg[8*i+0], a0); a0 = fmaf(v0.y, wreg[8*i+1], a0);
                a0 = fmaf(v0.z, wreg[8*i+2], a0); a0 = fmaf(v0.w, wreg[8*i+3], a0);
                a1 = fmaf(v1.x, wreg[8*i+4], a1); a1 = fmaf(v1.y, wreg[8*i+5], a1);
                a1 = fmaf(v1.z, wreg[8*i+6], a1); a1 = fmaf(v1.w, wreg[8*i+7], a1);
            }
            a0 = fmaf(inp[64], wreg[64], a0);
            a1 = fmaf(inp[65], wreg[65], a1);
            a0 = fmaf(inp[66], wreg[66], a0);
            dst[(size_t)(gbase + pt) * C + ch] = a0 + a1;
        }
    }
}

// ---------------- ball query: 3 radii, ordered compaction, early exit ----------------
__global__ void __launch_bounds__(128) ball_kernel(
    const float* __restrict__ xyz, const float* __restrict__ newxyz)
{
    const int bs = blockIdx.x;
    const int b = bs >> 10;
    const int tid = threadIdx.x;
    const int w = tid >> 5, lane = tid & 31;
    const float cx = newxyz[(size_t)bs*3+0];
    const float cy = newxyz[(size_t)bs*3+1];
    const float cz = newxyz[(size_t)bs*3+2];
    const float nn = __fadd_rn(__fadd_rn(__fmul_rn(cx,cx), __fmul_rn(cy,cy)), __fmul_rn(cz,cz));
    __shared__ int cnt[3], wcnt[3][4], sfirst[3];
    if (tid < 3){ cnt[tid] = 0; sfirst[tid] = 0; }
    __syncthreads();
    const float* xb = xyz + (size_t)b * NP * 3;

    for (int jb = 0; jb < NP; jb += 128){
        int j = jb + tid;
        float x = xb[3*j], y = xb[3*j+1], z = xb[3*j+2];
        float pp  = __fadd_rn(__fadd_rn(__fmul_rn(x,x), __fmul_rn(y,y)), __fmul_rn(z,z));
        float dot = __fadd_rn(__fadd_rn(__fmul_rn(cx,x), __fmul_rn(cy,y)), __fmul_rn(cz,z));
        float sqd = __fsub_rn(__fadd_rn(nn, pp), __fmul_rn(2.0f, dot));
        bool in0 = !(sqd > 0.01f);
        bool in1 = !(sqd > 0.04f);
        bool in2 = !(sqd > 0.16f);
        unsigned m0 = __ballot_sync(0xFFFFFFFFu, in0);
        unsigned m1 = __ballot_sync(0xFFFFFFFFu, in1);
        unsigned m2 = __ballot_sync(0xFFFFFFFFu, in2);
        if (lane == 0){ wcnt[0][w]=__popc(m0); wcnt[1][w]=__popc(m1); wcnt[2][w]=__popc(m2); }
        __syncthreads();
        unsigned lm = (1u << lane) - 1u;
        int b0 = cnt[0], b1 = cnt[1], b2 = cnt[2];
        for (int ww = 0; ww < w; ww++){ b0 += wcnt[0][ww]; b1 += wcnt[1][ww]; b2 += wcnt[2][ww]; }
        if (in0){ int p = b0 + __popc(m0 & lm); if (p == 0) sfirst[0] = j; if (p < 16)  gIdx0[(size_t)bs*16  + p] = j; }
        if (in1){ int p = b1 + __popc(m1 & lm); if (p == 0) sfirst[1] = j; if (p < 32)  gIdx1[(size_t)bs*32  + p] = j; }
        if (in2){ int p = b2 + __popc(m2 & lm); if (p == 0) sfirst[2] = j; if (p < 128) gIdx2[(size_t)bs*128 + p] = j; }
        __syncthreads();
        if (tid == 0){
            cnt[0] += wcnt[0][0]+wcnt[0][1]+wcnt[0][2]+wcnt[0][3];
            cnt[1] += wcnt[1][0]+wcnt[1][1]+wcnt[1][2]+wcnt[1][3];
            cnt[2] += wcnt[2][0]+wcnt[2][1]+wcnt[2][2]+wcnt[2][3];
        }
        __syncthreads();
        if (cnt[0] >= 16 && cnt[1] >= 32 && cnt[2] >= 128) break;
    }
    int f0 = sfirst[0], f1 = sfirst[1], f2 = sfirst[2];
    for (int q = cnt[0] + tid; q < 16;  q += 128) gIdx0[(size_t)bs*16  + q] = f0;
    for (int q = cnt[1] + tid; q < 32;  q += 128) gIdx1[(size_t)bs*32  + q] = f1;
    for (int q = cnt[2] + tid; q < 128; q += 128) gIdx2[(size_t)bs*128 + q] = f2;
}

// ---------------- fused MLP2+MLP3+maxpool: producer/consumer warps, double-buffered h2 ----------------
template<int SCALE, int K, int C1, int C2, int C3, int KT>
__global__ void __launch_bounds__(256) mlp_kernel(
    const float* __restrict__ w1,
    const float* __restrict__ w2, const float* __restrict__ b2,
    const float* __restrict__ w3, const float* __restrict__ b3,
    const float* __restrict__ newxyz, float* __restrict__ out, int off)
{
    const float* PQ  = (SCALE == 0) ? gPQ0  : (SCALE == 1) ? gPQ1  : gPQ2;
    const int*   IDX = (SCALE == 0) ? gIdx0 : (SCALE == 1) ? gIdx1 : gIdx2;

    __shared__ __align__(16) float h1s[K*C1];
    __shared__ __align__(16) float h2s[2][KT*C2];
    __shared__ __align__(16) float Rs[C1];
    __shared__ int nix[K];

    const int bs = blockIdx.x;
    const int b = bs >> 10;
    const int tid = threadIdx.x;

    if (tid < K) nix[tid] = IDX[(size_t)bs*K + tid];
    if (tid < C1){
        const float* wr = w1 + tid*67;
        const float* c = newxyz + (size_t)bs*3;
        Rs[tid] = fmaf(wr[2], c[2], fmaf(wr[1], c[1], wr[0]*c[0]));
    }
    __syncthreads();

    // h1 = relu(PQ[neighbor] - W1xyz @ center), float4 gather (L2 resident)
    constexpr int C1v = C1/4;
    const float4* PQ4 = reinterpret_cast<const float4*>(PQ + (size_t)b * NP * C1);
    float4* h14 = reinterpret_cast<float4*>(h1s);
    const float4* Rs4 = reinterpret_cast<const float4*>(Rs);
    for (int e = tid; e < K*C1v; e += 256){
        int r = e / C1v, c4 = e - r*C1v;
        float4 v = PQ4[(size_t)nix[r]*C1v + c4];
        float4 rv = Rs4[c4];
        v.x = fmaxf(v.x - rv.x, 0.f); v.y = fmaxf(v.y - rv.y, 0.f);
        v.z = fmaxf(v.z - rv.z, 0.f); v.w = fmaxf(v.w - rv.w, 0.f);
        h14[r*C1v + c4] = v;
    }
    __syncthreads();

    const bool isProd = (tid < C2);
    const bool isCons = (tid >= 128) && (tid < 128 + C3);
    const int cid = tid - 128;

    constexpr int WV = (C1 > C2 ? C1 : C2) / 4;
    float4 wr[WV];
    float bias = 0.f;
    if (isProd){
        const float4* wp = reinterpret_cast<const float4*>(w2 + tid*C1);
#pragma unroll
        for (int i = 0; i < C1/4; i++) wr[i] = wp[i];
        bias = b2[tid];
    } else if (isCons){
        const float4* wp = reinterpret_cast<const float4*>(w3 + cid*C2);
#pragma unroll
        for (int i = 0; i < C2/4; i++) wr[i] = wp[i];
        bias = b3[cid];
    }

    float m = 0.f;  // maxpool accumulator (relu fused: m >= 0)

    auto produce = [&](int t, int buf){
        for (int rr = 0; rr < KT; rr++){
            const float4* hp = reinterpret_cast<const float4*>(h1s + (t*KT + rr)*C1);
            float2 a0 = make_float2(0.f, 0.f), a1 = make_float2(0.f, 0.f);
#pragma unroll
            for (int i = 0; i < C1/8; i++){
                float4 ha = hp[2*i], hb = hp[2*i+1];
                a0 = ffma2(f2lo(ha), f2lo(wr[2*i]),   a0);
                a0 = ffma2(f2hi(ha), f2hi(wr[2*i]),   a0);
                a1 = ffma2(f2lo(hb), f2lo(wr[2*i+1]), a1);
                a1 = ffma2(f2hi(hb), f2hi(wr[2*i+1]), a1);
            }
            h2s[buf][rr*C2 + tid] = fmaxf((a0.x + a0.y) + (a1.x + a1.y) + bias, 0.f);
        }
    };
    auto consume = [&](int buf){
        for (int rr = 0; rr < KT; rr++){
            const float4* hp = reinterpret_cast<const float4*>(&h2s[buf][rr*C2]);
            float2 a0 = make_float2(0.f, 0.f), a1 = make_float2(0.f, 0.f);
#pragma unroll
            for (int i = 0; i < C2/8; i++){
                float4 ha = hp[2*i], hb = hp[2*i+1];
                a0 = ffma2(f2lo(ha), f2lo(wr[2*i]),   a0);
                a0 = ffma2(f2hi(ha), f2hi(wr[2*i]),   a0);
                a1 = ffma2(f2lo(hb), f2lo(wr[2*i+1]), a1);
                a1 = ffma2(f2hi(hb), f2hi(wr[2*i+1]), a1);
            }
            m = fmaxf(m, (a0.x + a0.y) + (a1.x + a1.y) + bias);
        }
    };

    constexpr int T = K / KT;
    if (isProd) produce(0, 0);
    __syncthreads();
#pragma unroll 1
    for (int t = 0; t < T; t++){
        if (isProd && (t + 1 < T)) produce(t + 1, (t + 1) & 1);
        if (isCons) consume(t & 1);
        __syncthreads();
    }
    if (isCons) out[(size_t)bs*320 + off + cid] = m;
}

// ---------------- launch ----------------
extern "C" void kernel_launch(void* const* d_in, const int* in_sizes, int n_in,
                              void* d_out, int out_size)
{
    const float* xyz  = (const float*)d_in[0];
    const float* feat = (const float*)d_in[1];
    const float* W[3][3]; const float* Bi[3][3];
    for (int i = 0; i < 3; i++)
        for (int j = 0; j < 3; j++){
            W[i][j]  = (const float*)d_in[2 + i*6 + j*2];
            Bi[i][j] = (const float*)d_in[3 + i*6 + j*2];
        }
    float* newxyz   = (float*)d_out;                 // (B, S, 3)
    float* feat_out = (float*)d_out + NB*NS*3;       // (B, S, 320)

    fps_kernel<<<NB, 1024>>>(xyz, newxyz);
    pq_kernel<<<NB*NP/32, 160>>>(xyz, feat,
        W[0][0], Bi[0][0], W[1][0], Bi[1][0], W[2][0], Bi[2][0]);
    ball_kernel<<<NB*NS, 128>>>(xyz, newxyz);

    mlp_kernel<0, 16,  32, 32, 64,  8><<<NB*NS, 256>>>(
        W[0][0], W[0][1], Bi[0][1], W[0][2], Bi[0][2], newxyz, feat_out, 0);
    mlp_kernel<1, 32,  64, 64, 128, 16><<<NB*NS, 256>>>(
        W[1][0], W[1][1], Bi[1][1], W[1][2], Bi[1][2], newxyz, feat_out, 64);
    mlp_kernel<2, 128, 64, 96, 128, 16><<<NB*NS, 256>>>(
        W[2][0], W[2][1], Bi[2][1], W[2][2], Bi[2][2], newxyz, feat_out, 192);
}

// round 6
// speedup vs baseline: 1.2581x; 1.2581x over previous
#include <cuda_runtime.h>

#define NB 8
#define NP 4096
#define NS 1024

// ---------------- device scratch (static: no allocation allowed) ----------------
__device__ float gPQ0[NB*NP*32];
__device__ float gPQ1[NB*NP*64];
__device__ float gPQ2[NB*NP*64];
__device__ int   gIdx0[NB*NS*16];
__device__ int   gIdx1[NB*NS*32];
__device__ int   gIdx2[NB*NS*128];

// packed fp32x2 FMA (sm_100+): 2 MACs/instr
__device__ __forceinline__ float2 ffma2(float2 a, float2 b, float2 c){
    unsigned long long au, bu, cu, du;
    au = *reinterpret_cast<const unsigned long long*>(&a);
    bu = *reinterpret_cast<const unsigned long long*>(&b);
    cu = *reinterpret_cast<const unsigned long long*>(&c);
    asm("fma.rn.f32x2 %0, %1, %2, %3;" : "=l"(du) : "l"(au), "l"(bu), "l"(cu));
    return *reinterpret_cast<float2*>(&du);
}
__device__ __forceinline__ float2 f2lo(float4 v){ return make_float2(v.x, v.y); }
__device__ __forceinline__ float2 f2hi(float4 v){ return make_float2(v.z, v.w); }

// ---------------- FPS: 1 CTA/batch, 1024-step sequential chain (unchanged, passing) ----------------
__global__ void __launch_bounds__(1024) fps_kernel(
    const float* __restrict__ xyz, float* __restrict__ newxyz)
{
    __shared__ unsigned long long swarp[32];
    __shared__ float scent[3];
    __shared__ unsigned swidx;
    const int b = blockIdx.x, tid = threadIdx.x;
    const float* xb = xyz + (size_t)b * NP * 3;

    float px[4], py[4], pz[4], dist[4];
#pragma unroll
    for (int i = 0; i < 4; i++){
        int p = tid + 1024*i;
        px[i] = xb[3*p]; py[i] = xb[3*p+1]; pz[i] = xb[3*p+2];
        dist[i] = 1e10f;
    }
    if (tid == 0){ scent[0] = px[0]; scent[1] = py[0]; scent[2] = pz[0]; }
    __syncthreads();

    for (int it = 0; it < NS; ++it){
        float cx = scent[0], cy = scent[1], cz = scent[2];
        if (tid == 0){
            float* o = newxyz + ((size_t)b * NS + it) * 3;
            o[0] = cx; o[1] = cy; o[2] = cz;
        }
        unsigned long long best = 0ull;
#pragma unroll
        for (int i = 0; i < 4; i++){
            float dx = px[i]-cx, dy = py[i]-cy, dz = pz[i]-cz;
            float d = __fadd_rn(__fadd_rn(__fmul_rn(dx,dx), __fmul_rn(dy,dy)), __fmul_rn(dz,dz));
            float nd = fminf(dist[i], d);
            dist[i] = nd;
            unsigned long long key = ((unsigned long long)__float_as_uint(nd) << 32)
                                   | (unsigned long long)(0xFFFFFFFFu - (unsigned)(tid + 1024*i));
            if (key > best) best = key;
        }
#pragma unroll
        for (int off = 16; off; off >>= 1){
            unsigned long long o = __shfl_down_sync(0xFFFFFFFFu, best, off);
            if (o > best) best = o;
        }
        if ((tid & 31) == 0) swarp[tid >> 5] = best;
        __syncthreads();
        if (tid < 32){
            unsigned long long v = swarp[tid];
#pragma unroll
            for (int off = 16; off; off >>= 1){
                unsigned long long o = __shfl_down_sync(0xFFFFFFFFu, v, off);
                if (o > v) v = o;
            }
            if (tid == 0) swidx = 0xFFFFFFFFu - (unsigned)(v & 0xFFFFFFFFull);
        }
        __syncthreads();
        unsigned w = swidx;
        if (tid == (w & 1023)){
            int slot = w >> 10;
            scent[0] = (slot==0) ? px[0] : (slot==1) ? px[1] : (slot==2) ? px[2] : px[3];
            scent[1] = (slot==0) ? py[0] : (slot==1) ? py[1] : (slot==2) ? py[2] : py[3];
            scent[2] = (slot==0) ? pz[0] : (slot==1) ? pz[1] : (slot==2) ? pz[2] : pz[3];
        }
        __syncthreads();
    }
}

// ---------------- PQ[n] = W1 @ [xyz_n; feat_n] + b1 (unchanged, passing) ----------------
__global__ void __launch_bounds__(160) pq_kernel(
    const float* __restrict__ xyz, const float* __restrict__ feat,
    const float* __restrict__ w00, const float* __restrict__ b00,
    const float* __restrict__ w10, const float* __restrict__ b10,
    const float* __restrict__ w20, const float* __restrict__ b20)
{
    __shared__ float sin_[8*68];
    const int tid = threadIdx.x;
    const float* wrow; float bias; float* dst; int C, ch;
    if (tid < 32)      { wrow = w00 + tid*67;      bias = b00[tid];    dst = gPQ0; C = 32; ch = tid; }
    else if (tid < 96) { wrow = w10 + (tid-32)*67; bias = b10[tid-32]; dst = gPQ1; C = 64; ch = tid-32; }
    else               { wrow = w20 + (tid-96)*67; bias = b20[tid-96]; dst = gPQ2; C = 64; ch = tid-96; }
    float wreg[67];
#pragma unroll
    for (int i = 0; i < 67; i++) wreg[i] = wrow[i];

    for (int grp = 0; grp < 4; grp++){
        int gbase = blockIdx.x * 32 + grp * 8;
        __syncthreads();
        for (int t = tid; t < 8*67; t += 160){
            int pt = t / 67, c = t - 67*pt;
            int g = gbase + pt;
            sin_[pt*68 + c] = (c < 3) ? xyz[(size_t)g*3 + c] : feat[(size_t)g*64 + (c-3)];
        }
        __syncthreads();
#pragma unroll 1
        for (int pt = 0; pt < 8; pt++){
            const float* inp = &sin_[pt*68];
            float a0 = bias, a1 = 0.f;
#pragma unroll
            for (int i = 0; i < 8; i++){
                float4 v0 = *reinterpret_cast<const float4*>(inp + 8*i);
                float4 v1 = *reinterpret_cast<const float4*>(inp + 8*i + 4);
                a0 = fmaf(v0.x, wreg[8*i+0], a0); a0 = fmaf(v0.y, wreg[8*i+1], a0);
                a0 = fmaf(v0.z, wreg[8*i+2], a0); a0 = fmaf(v0.w, wreg[8*i+3], a0);
                a1 = fmaf(v1.x, wreg[8*i+4], a1); a1 = fmaf(v1.y, wreg[8*i+5], a1);
                a1 = fmaf(v1.z, wreg[8*i+6], a1); a1 = fmaf(v1.w, wreg[8*i+7], a1);
            }
            a0 = fmaf(inp[64], wreg[64], a0);
            a1 = fmaf(inp[65], wreg[65], a1);
            a0 = fmaf(inp[66], wreg[66], a0);
            dst[(size_t)(gbase + pt) * C + ch] = a0 + a1;
        }
    }
}

// ---------------- ball query (unchanged, passing) ----------------
__global__ void __launch_bounds__(128) ball_kernel(
    const float* __restrict__ xyz, const float* __restrict__ newxyz)
{
    const int bs = blockIdx.x;
    const int b = bs >> 10;
    const int tid = threadIdx.x;
    const int w = tid >> 5, lane = tid & 31;
    const float cx = newxyz[(size_t)bs*3+0];
    const float cy = newxyz[(size_t)bs*3+1];
    const float cz = newxyz[(size_t)bs*3+2];
    const float nn = __fadd_rn(__fadd_rn(__fmul_rn(cx,cx), __fmul_rn(cy,cy)), __fmul_rn(cz,cz));
    __shared__ int cnt[3], wcnt[3][4], sfirst[3];
    if (tid < 3){ cnt[tid] = 0; sfirst[tid] = 0; }
    __syncthreads();
    const float* xb = xyz + (size_t)b * NP * 3;

    for (int jb = 0; jb < NP; jb += 128){
        int j = jb + tid;
        float x = xb[3*j], y = xb[3*j+1], z = xb[3*j+2];
        float pp  = __fadd_rn(__fadd_rn(__fmul_rn(x,x), __fmul_rn(y,y)), __fmul_rn(z,z));
        float dot = __fadd_rn(__fadd_rn(__fmul_rn(cx,x), __fmul_rn(cy,y)), __fmul_rn(cz,z));
        float sqd = __fsub_rn(__fadd_rn(nn, pp), __fmul_rn(2.0f, dot));
        bool in0 = !(sqd > 0.01f);
        bool in1 = !(sqd > 0.04f);
        bool in2 = !(sqd > 0.16f);
        unsigned m0 = __ballot_sync(0xFFFFFFFFu, in0);
        unsigned m1 = __ballot_sync(0xFFFFFFFFu, in1);
        unsigned m2 = __ballot_sync(0xFFFFFFFFu, in2);
        if (lane == 0){ wcnt[0][w]=__popc(m0); wcnt[1][w]=__popc(m1); wcnt[2][w]=__popc(m2); }
        __syncthreads();
        unsigned lm = (1u << lane) - 1u;
        int b0 = cnt[0], b1 = cnt[1], b2 = cnt[2];
        for (int ww = 0; ww < w; ww++){ b0 += wcnt[0][ww]; b1 += wcnt[1][ww]; b2 += wcnt[2][ww]; }
        if (in0){ int p = b0 + __popc(m0 & lm); if (p == 0) sfirst[0] = j; if (p < 16)  gIdx0[(size_t)bs*16  + p] = j; }
        if (in1){ int p = b1 + __popc(m1 & lm); if (p == 0) sfirst[1] = j; if (p < 32)  gIdx1[(size_t)bs*32  + p] = j; }
        if (in2){ int p = b2 + __popc(m2 & lm); if (p == 0) sfirst[2] = j; if (p < 128) gIdx2[(size_t)bs*128 + p] = j; }
        __syncthreads();
        if (tid == 0){
            cnt[0] += wcnt[0][0]+wcnt[0][1]+wcnt[0][2]+wcnt[0][3];
            cnt[1] += wcnt[1][0]+wcnt[1][1]+wcnt[1][2]+wcnt[1][3];
            cnt[2] += wcnt[2][0]+wcnt[2][1]+wcnt[2][2]+wcnt[2][3];
        }
        __syncthreads();
        if (cnt[0] >= 16 && cnt[1] >= 32 && cnt[2] >= 128) break;
    }
    int f0 = sfirst[0], f1 = sfirst[1], f2 = sfirst[2];
    for (int q = cnt[0] + tid; q < 16;  q += 128) gIdx0[(size_t)bs*16  + q] = f0;
    for (int q = cnt[1] + tid; q < 32;  q += 128) gIdx1[(size_t)bs*32  + q] = f1;
    for (int q = cnt[2] + tid; q < 128; q += 128) gIdx2[(size_t)bs*128 + q] = f2;
}

// ---------------- register-tiled fused MLP2+MLP3+maxpool ----------------
// BC centers per CTA; rows R = BC*K; h1/h2/weights in (padded) dynamic smem;
// per-thread TRxTC float2 accumulators; ffma2 throughout.
template<int SCALE,int BC,int K,int C1,int C2,int C3,int P1,int P2,
         int GR2,int GC2,int GR3,int GC3>
__global__ void __launch_bounds__(256,1) mlp_kernel(
    const float* __restrict__ w1,
    const float* __restrict__ w2, const float* __restrict__ b2,
    const float* __restrict__ w3, const float* __restrict__ b3,
    const float* __restrict__ newxyz, float* __restrict__ out, int off)
{
    constexpr int R = BC*K;
    const float* PQ  = (SCALE==0) ? gPQ0  : (SCALE==1) ? gPQ1  : gPQ2;
    const int*   IDX = (SCALE==0) ? gIdx0 : (SCALE==1) ? gIdx1 : gIdx2;

    extern __shared__ float sm[];
    float* h1  = sm;                    // R  * P1
    float* h2  = h1  + R*P1;            // R  * P2
    float* w2s = h2  + R*P2;            // C2 * P1
    float* w3s = w2s + C2*P1;           // C3 * P2
    float* Rs  = w3s + C3*P2;           // BC * C1
    int*   nix = (int*)(Rs + BC*C1);    // R
    int*   mbuf= nix + R;               // BC * C3

    const int tid = threadIdx.x;
    const int bs0 = blockIdx.x * BC;
    const int b   = bs0 >> 10;

    // stage weights into padded smem (float4)
    for (int e = tid; e < C2*(C1/4); e += 256){
        int c = e/(C1/4), q = e - c*(C1/4);
        *reinterpret_cast<float4*>(&w2s[c*P1 + 4*q]) = reinterpret_cast<const float4*>(w2)[e];
    }
    for (int e = tid; e < C3*(C2/4); e += 256){
        int c = e/(C2/4), q = e - c*(C2/4);
        *reinterpret_cast<float4*>(&w3s[c*P2 + 4*q]) = reinterpret_cast<const float4*>(w3)[e];
    }
    for (int e = tid; e < R; e += 256) nix[e] = IDX[(size_t)bs0*K + e];
    for (int e = tid; e < BC*C3; e += 256) mbuf[e] = 0;   // int 0 == float 0.0f (relu floor)
    if (tid < BC*C1){
        int c = tid / C1, ch = tid - c*C1;
        const float* wr = w1 + ch*67;
        const float* ce = newxyz + (size_t)(bs0 + c)*3;
        Rs[tid] = fmaf(wr[2], ce[2], fmaf(wr[1], ce[1], wr[0]*ce[0]));
    }
    __syncthreads();

    // gather + h1 = relu(PQ[nix] - Rs)
    {
        constexpr int C1v = C1/4;
        const float4* PQ4 = reinterpret_cast<const float4*>(PQ + (size_t)b * NP * C1);
        for (int e = tid; e < R*C1v; e += 256){
            int r = e / C1v, q = e - r*C1v;
            float4 v  = PQ4[(size_t)nix[r]*C1v + q];
            float4 rv = *reinterpret_cast<const float4*>(&Rs[(r/K)*C1 + 4*q]);
            v.x = fmaxf(v.x - rv.x, 0.f); v.y = fmaxf(v.y - rv.y, 0.f);
            v.z = fmaxf(v.z - rv.z, 0.f); v.w = fmaxf(v.w - rv.w, 0.f);
            *reinterpret_cast<float4*>(&h1[r*P1 + 4*q]) = v;
        }
    }
    __syncthreads();

    // ---- layer 2: H2[R x C2] = relu(H1 @ W2^T + b2) ----
    {
        constexpr int TR = R/GR2, TC = C2/GC2;
        const int tr = tid / GC2, tc = tid - (tid / GC2)*GC2;
        float2 acc[TR][TC];
#pragma unroll
        for (int i = 0; i < TR; i++)
#pragma unroll
            for (int j = 0; j < TC; j++) acc[i][j] = make_float2(0.f, 0.f);
#pragma unroll 1
        for (int kk = 0; kk < C1; kk += 4){
            float4 a[TR];
#pragma unroll
            for (int i = 0; i < TR; i++)
                a[i] = *reinterpret_cast<const float4*>(&h1[(tr + GR2*i)*P1 + kk]);
#pragma unroll
            for (int j = 0; j < TC; j++){
                float4 w = *reinterpret_cast<const float4*>(&w2s[(tc + GC2*j)*P1 + kk]);
#pragma unroll
                for (int i = 0; i < TR; i++){
                    acc[i][j] = ffma2(f2lo(a[i]), f2lo(w), acc[i][j]);
                    acc[i][j] = ffma2(f2hi(a[i]), f2hi(w), acc[i][j]);
                }
            }
        }
#pragma unroll
        for (int j = 0; j < TC; j++){
            float bb = b2[tc + GC2*j];
#pragma unroll
            for (int i = 0; i < TR; i++)
                h2[(tr + GR2*i)*P2 + tc + GC2*j] = fmaxf(acc[i][j].x + acc[i][j].y + bb, 0.f);
        }
    }
    __syncthreads();

    // ---- layer 3 + fused maxpool over k (per center) ----
    {
        constexpr int TR = R/GR3, TC = C3/GC3;
        const int tr = tid / GC3, tc = tid - (tid / GC3)*GC3;
        float2 acc[TR][TC];
#pragma unroll
        for (int i = 0; i < TR; i++)
#pragma unroll
            for (int j = 0; j < TC; j++) acc[i][j] = make_float2(0.f, 0.f);
#pragma unroll 1
        for (int kk = 0; kk < C2; kk += 4){
            float4 a[TR];
#pragma unroll
            for (int i = 0; i < TR; i++)
                a[i] = *reinterpret_cast<const float4*>(&h2[(tr + GR3*i)*P2 + kk]);
#pragma unroll
            for (int j = 0; j < TC; j++){
                float4 w = *reinterpret_cast<const float4*>(&w3s[(tc + GC3*j)*P2 + kk]);
#pragma unroll
                for (int i = 0; i < TR; i++){
                    acc[i][j] = ffma2(f2lo(a[i]), f2lo(w), acc[i][j]);
                    acc[i][j] = ffma2(f2hi(a[i]), f2hi(w), acc[i][j]);
                }
            }
        }
#pragma unroll
        for (int j = 0; j < TC; j++){
            float bb = b3[tc + GC3*j];
            float vm = -1e30f;
            int prevc = tr / K;
#pragma unroll
            for (int i = 0; i < TR; i++){
                int cen = (tr + GR3*i) / K;
                if (cen != prevc){
                    atomicMax(&mbuf[prevc*C3 + tc + GC3*j], __float_as_int(vm));
                    vm = -1e30f; prevc = cen;
                }
                vm = fmaxf(vm, acc[i][j].x + acc[i][j].y + bb);
            }
            atomicMax(&mbuf[prevc*C3 + tc + GC3*j], __float_as_int(vm));
        }
    }
    __syncthreads();

    for (int e = tid; e < BC*C3; e += 256){
        int c = e / C3, col = e - c*C3;
        out[(size_t)(bs0 + c)*320 + off + col] = __int_as_float(mbuf[e]);
    }
}

// smem sizes (bytes): floats(h1+h2+w2s+w3s+Rs) + ints(nix+mbuf)
template<int BC,int K,int C1,int C2,int C3,int P1,int P2>
constexpr int mlp_smem(){
    return (BC*K*P1 + BC*K*P2 + C2*P1 + C3*P2 + BC*C1)*4 + (BC*K + BC*C3)*4;
}

// ---------------- launch ----------------
extern "C" void kernel_launch(void* const* d_in, const int* in_sizes, int n_in,
                              void* d_out, int out_size)
{
    const float* xyz  = (const float*)d_in[0];
    const float* feat = (const float*)d_in[1];
    const float* W[3][3]; const float* Bi[3][3];
    for (int i = 0; i < 3; i++)
        for (int j = 0; j < 3; j++){
            W[i][j]  = (const float*)d_in[2 + i*6 + j*2];
            Bi[i][j] = (const float*)d_in[3 + i*6 + j*2];
        }
    float* newxyz   = (float*)d_out;                 // (B, S, 3)
    float* feat_out = (float*)d_out + NB*NS*3;       // (B, S, 320)

    // scale0: BC=8,K=16,C=32/32/64, P=36/36; L2 grid 16x16 (TR8,TC2); L3 16x16 (TR8,TC4)
    constexpr int SM0 = mlp_smem<8,16,32,32,64,36,36>();
    // scale1: BC=2,K=32,C=64/64/128, P=68/68; L2 16x16 (TR4,TC4); L3 8x32 (TR8,TC4)
    constexpr int SM1 = mlp_smem<2,32,64,64,128,68,68>();
    // scale2: BC=1,K=128,C=64/96/128, P=68/100; L2 16x16 (TR8,TC6); L3 16x16 (TR8,TC8)
    constexpr int SM2 = mlp_smem<1,128,64,96,128,68,100>();

    cudaFuncSetAttribute((const void*)mlp_kernel<0,8,16,32,32,64,36,36,16,16,16,16>,
                         cudaFuncAttributeMaxDynamicSharedMemorySize, SM0);
    cudaFuncSetAttribute((const void*)mlp_kernel<1,2,32,64,64,128,68,68,16,16,8,32>,
                         cudaFuncAttributeMaxDynamicSharedMemorySize, SM1);
    cudaFuncSetAttribute((const void*)mlp_kernel<2,1,128,64,96,128,68,100,16,16,16,16>,
                         cudaFuncAttributeMaxDynamicSharedMemorySize, SM2);

    fps_kernel<<<NB, 1024>>>(xyz, newxyz);
    pq_kernel<<<NB*NP/32, 160>>>(xyz, feat,
        W[0][0], Bi[0][0], W[1][0], Bi[1][0], W[2][0], Bi[2][0]);
    ball_kernel<<<NB*NS, 128>>>(xyz, newxyz);

    mlp_kernel<0,8,16,32,32,64,36,36,16,16,16,16><<<NB*NS/8, 256, SM0>>>(
        W[0][0], W[0][1], Bi[0][1], W[0][2], Bi[0][2], newxyz, feat_out, 0);
    mlp_kernel<1,2,32,64,64,128,68,68,16,16,8,32><<<NB*NS/2, 256, SM1>>>(
        W[1][0], W[1][1], Bi[1][1], W[1][2], Bi[1][2], newxyz, feat_out, 64);
    mlp_kernel<2,1,128,64,96,128,68,100,16,16,16,16><<<NB*NS, 256, SM2>>>(
        W[2][0], W[2][1], Bi[2][1], W[2][2], Bi[2][2], newxyz, feat_out, 192);
}

// round 8
// speedup vs baseline: 1.2910x; 1.0261x over previous
#include <cuda_runtime.h>

#define NB 8
#define NP 4096
#define NS 1024

// ---------------- device scratch (static: no allocation allowed) ----------------
__device__ float gPQ0[NB*NP*32];
__device__ float gPQ1[NB*NP*64];
__device__ float gPQ2[NB*NP*64];
__device__ int   gIdx0[NB*NS*16];
__device__ int   gIdx1[NB*NS*32];
__device__ int   gIdx2[NB*NS*128];

// packed fp32x2 FMA (sm_100+): 2 MACs/instr
__device__ __forceinline__ float2 ffma2(float2 a, float2 b, float2 c){
    unsigned long long au, bu, cu, du;
    au = *reinterpret_cast<const unsigned long long*>(&a);
    bu = *reinterpret_cast<const unsigned long long*>(&b);
    cu = *reinterpret_cast<const unsigned long long*>(&c);
    asm("fma.rn.f32x2 %0, %1, %2, %3;" : "=l"(du) : "l"(au), "l"(bu), "l"(cu));
    return *reinterpret_cast<float2*>(&du);
}
__device__ __forceinline__ float2 f2lo(float4 v){ return make_float2(v.x, v.y); }
__device__ __forceinline__ float2 f2hi(float4 v){ return make_float2(v.z, v.w); }

// ---------------- FPS: 1 CTA/batch, 2 barriers per step, coords in smem ----------------
__global__ void __launch_bounds__(1024) fps_kernel(
    const float* __restrict__ xyz, float* __restrict__ newxyz)
{
    extern __shared__ float sfm[];           // sx[NP], sy[NP], sz[NP]
    __shared__ unsigned long long swarp[32];
    __shared__ float scent[3];
    float* sx = sfm; float* sy = sfm + NP; float* sz = sfm + 2*NP;

    const int b = blockIdx.x, tid = threadIdx.x;
    const float* xb = xyz + (size_t)b * NP * 3;

    float px[4], py[4], pz[4], dist[4];
#pragma unroll
    for (int i = 0; i < 4; i++){
        int p = tid + 1024*i;
        px[i] = xb[3*p]; py[i] = xb[3*p+1]; pz[i] = xb[3*p+2];
        sx[p] = px[i]; sy[p] = py[i]; sz[p] = pz[i];
        dist[i] = 1e10f;
    }
    if (tid == 0){ scent[0] = px[0]; scent[1] = py[0]; scent[2] = pz[0]; }
    __syncthreads();

    for (int it = 0; it < NS; ++it){
        const float cx = scent[0], cy = scent[1], cz = scent[2];
        if (tid == 0){
            float* o = newxyz + ((size_t)b * NS + it) * 3;
            o[0] = cx; o[1] = cy; o[2] = cz;
        }
        // best-of-4 with strict > (keeps smallest index on ties; idx increases with i)
        float m; unsigned mi;
#pragma unroll
        for (int i = 0; i < 4; i++){
            float dx = px[i]-cx, dy = py[i]-cy, dz = pz[i]-cz;
            // exact reference arithmetic: separate-rounded squares, left-to-right sum
            float d = __fadd_rn(__fadd_rn(__fmul_rn(dx,dx), __fmul_rn(dy,dy)), __fmul_rn(dz,dz));
            float nd = fminf(dist[i], d);
            dist[i] = nd;
            if (i == 0){ m = nd; mi = (unsigned)tid; }
            else if (nd > m){ m = nd; mi = (unsigned)(tid + 1024*i); }
        }
        unsigned long long best = ((unsigned long long)__float_as_uint(m) << 32)
                                | (unsigned long long)(0xFFFFFFFFu - mi);
#pragma unroll
        for (int off = 16; off; off >>= 1){
            unsigned long long o = __shfl_down_sync(0xFFFFFFFFu, best, off);
            if (o > best) best = o;
        }
        if ((tid & 31) == 0) swarp[tid >> 5] = best;
        __syncthreads();
        if (tid < 32){
            unsigned long long v = swarp[tid];
#pragma unroll
            for (int off = 16; off; off >>= 1){
                unsigned long long o = __shfl_down_sync(0xFFFFFFFFu, v, off);
                if (o > v) v = o;
            }
            if (tid == 0){
                unsigned w = 0xFFFFFFFFu - (unsigned)(v & 0xFFFFFFFFull);
                scent[0] = sx[w]; scent[1] = sy[w]; scent[2] = sz[w];
            }
        }
        __syncthreads();
    }
}

// ---------------- PQ[n] = W1 @ [xyz_n; feat_n] + b1 (unchanged, passing) ----------------
__global__ void __launch_bounds__(160) pq_kernel(
    const float* __restrict__ xyz, const float* __restrict__ feat,
    const float* __restrict__ w00, const float* __restrict__ b00,
    const float* __restrict__ w10, const float* __restrict__ b10,
    const float* __restrict__ w20, const float* __restrict__ b20)
{
    __shared__ float sin_[8*68];
    const int tid = threadIdx.x;
    const float* wrow; float bias; float* dst; int C, ch;
    if (tid < 32)      { wrow = w00 + tid*67;      bias = b00[tid];    dst = gPQ0; C = 32; ch = tid; }
    else if (tid < 96) { wrow = w10 + (tid-32)*67; bias = b10[tid-32]; dst = gPQ1; C = 64; ch = tid-32; }
    else               { wrow = w20 + (tid-96)*67; bias = b20[tid-96]; dst = gPQ2; C = 64; ch = tid-96; }
    float wreg[67];
#pragma unroll
    for (int i = 0; i < 67; i++) wreg[i] = wrow[i];

    for (int grp = 0; grp < 4; grp++){
        int gbase = blockIdx.x * 32 + grp * 8;
        __syncthreads();
        for (int t = tid; t < 8*67; t += 160){
            int pt = t / 67, c = t - 67*pt;
            int g = gbase + pt;
            sin_[pt*68 + c] = (c < 3) ? xyz[(size_t)g*3 + c] : feat[(size_t)g*64 + (c-3)];
        }
        __syncthreads();
#pragma unroll 1
        for (int pt = 0; pt < 8; pt++){
            const float* inp = &sin_[pt*68];
            float a0 = bias, a1 = 0.f;
#pragma unroll
            for (int i = 0; i < 8; i++){
                float4 v0 = *reinterpret_cast<const float4*>(inp + 8*i);
                float4 v1 = *reinterpret_cast<const float4*>(inp + 8*i + 4);
                a0 = fmaf(v0.x, wreg[8*i+0], a0); a0 = fmaf(v0.y, wreg[8*i+1], a0);
                a0 = fmaf(v0.z, wreg[8*i+2], a0); a0 = fmaf(v0.w, wreg[8*i+3], a0);
                a1 = fmaf(v1.x, wreg[8*i+4], a1); a1 = fmaf(v1.y, wreg[8*i+5], a1);
                a1 = fmaf(v1.z, wreg[8*i+6], a1); a1 = fmaf(v1.w, wreg[8*i+7], a1);
            }
            a0 = fmaf(inp[64], wreg[64], a0);
            a1 = fmaf(inp[65], wreg[65], a1);
            a0 = fmaf(inp[66], wreg[66], a0);
            dst[(size_t)(gbase + pt) * C + ch] = a0 + a1;
        }
    }
}

// ---------------- ball query (unchanged, passing) ----------------
__global__ void __launch_bounds__(128) ball_kernel(
    const float* __restrict__ xyz, const float* __restrict__ newxyz)
{
    const int bs = blockIdx.x;
    const int b = bs >> 10;
    const int tid = threadIdx.x;
    const int w = tid >> 5, lane = tid & 31;
    const float cx = newxyz[(size_t)bs*3+0];
    const float cy = newxyz[(size_t)bs*3+1];
    const float cz = newxyz[(size_t)bs*3+2];
    const float nn = __fadd_rn(__fadd_rn(__fmul_rn(cx,cx), __fmul_rn(cy,cy)), __fmul_rn(cz,cz));
    __shared__ int cnt[3], wcnt[3][4], sfirst[3];
    if (tid < 3){ cnt[tid] = 0; sfirst[tid] = 0; }
    __syncthreads();
    const float* xb = xyz + (size_t)b * NP * 3;

    for (int jb = 0; jb < NP; jb += 128){
        int j = jb + tid;
        float x = xb[3*j], y = xb[3*j+1], z = xb[3*j+2];
        float pp  = __fadd_rn(__fadd_rn(__fmul_rn(x,x), __fmul_rn(y,y)), __fmul_rn(z,z));
        float dot = __fadd_rn(__fadd_rn(__fmul_rn(cx,x), __fmul_rn(cy,y)), __fmul_rn(cz,z));
        float sqd = __fsub_rn(__fadd_rn(nn, pp), __fmul_rn(2.0f, dot));
        bool in0 = !(sqd > 0.01f);
        bool in1 = !(sqd > 0.04f);
        bool in2 = !(sqd > 0.16f);
        unsigned m0 = __ballot_sync(0xFFFFFFFFu, in0);
        unsigned m1 = __ballot_sync(0xFFFFFFFFu, in1);
        unsigned m2 = __ballot_sync(0xFFFFFFFFu, in2);
        if (lane == 0){ wcnt[0][w]=__popc(m0); wcnt[1][w]=__popc(m1); wcnt[2][w]=__popc(m2); }
        __syncthreads();
        unsigned lm = (1u << lane) - 1u;
        int b0 = cnt[0], b1 = cnt[1], b2 = cnt[2];
        for (int ww = 0; ww < w; ww++){ b0 += wcnt[0][ww]; b1 += wcnt[1][ww]; b2 += wcnt[2][ww]; }
        if (in0){ int p = b0 + __popc(m0 & lm); if (p == 0) sfirst[0] = j; if (p < 16)  gIdx0[(size_t)bs*16  + p] = j; }
        if (in1){ int p = b1 + __popc(m1 & lm); if (p == 0) sfirst[1] = j; if (p < 32)  gIdx1[(size_t)bs*32  + p] = j; }
        if (in2){ int p = b2 + __popc(m2 & lm); if (p == 0) sfirst[2] = j; if (p < 128) gIdx2[(size_t)bs*128 + p] = j; }
        __syncthreads();
        if (tid == 0){
            cnt[0] += wcnt[0][0]+wcnt[0][1]+wcnt[0][2]+wcnt[0][3];
            cnt[1] += wcnt[1][0]+wcnt[1][1]+wcnt[1][2]+wcnt[1][3];
            cnt[2] += wcnt[2][0]+wcnt[2][1]+wcnt[2][2]+wcnt[2][3];
        }
        __syncthreads();
        if (cnt[0] >= 16 && cnt[1] >= 32 && cnt[2] >= 128) break;
    }
    int f0 = sfirst[0], f1 = sfirst[1], f2 = sfirst[2];
    for (int q = cnt[0] + tid; q < 16;  q += 128) gIdx0[(size_t)bs*16  + q] = f0;
    for (int q = cnt[1] + tid; q < 32;  q += 128) gIdx1[(size_t)bs*32  + q] = f1;
    for (int q = cnt[2] + tid; q < 128; q += 128) gIdx2[(size_t)bs*128 + q] = f2;
}

// ---------------- register-tiled fused MLP2+MLP3+maxpool ----------------
template<int SCALE,int NT,int BC,int K,int C1,int C2,int C3,int P1,int P2,
         int GR2,int GC2,int GR3,int GC3>
__global__ void __launch_bounds__(NT,1) mlp_kernel(
    const float* __restrict__ w1,
    const float* __restrict__ w2, const float* __restrict__ b2,
    const float* __restrict__ w3, const float* __restrict__ b3,
    const float* __restrict__ newxyz, float* __restrict__ out, int off)
{
    constexpr int R = BC*K;
    const float* PQ  = (SCALE==0) ? gPQ0  : (SCALE==1) ? gPQ1  : gPQ2;
    const int*   IDX = (SCALE==0) ? gIdx0 : (SCALE==1) ? gIdx1 : gIdx2;

    extern __shared__ float sm[];
    float* h1  = sm;                    // R  * P1
    float* h2  = h1  + R*P1;            // R  * P2
    float* w2s = h2  + R*P2;            // C2 * P1
    float* w3s = w2s + C2*P1;           // C3 * P2
    float* Rs  = w3s + C3*P2;           // BC * C1
    int*   nix = (int*)(Rs + BC*C1);    // R
    int*   mbuf= nix + R;               // BC * C3

    const int tid = threadIdx.x;
    const int bs0 = blockIdx.x * BC;
    const int b   = bs0 >> 10;

    for (int e = tid; e < C2*(C1/4); e += NT){
        int c = e/(C1/4), q = e - c*(C1/4);
        *reinterpret_cast<float4*>(&w2s[c*P1 + 4*q]) = reinterpret_cast<const float4*>(w2)[e];
    }
    for (int e = tid; e < C3*(C2/4); e += NT){
        int c = e/(C2/4), q = e - c*(C2/4);
        *reinterpret_cast<float4*>(&w3s[c*P2 + 4*q]) = reinterpret_cast<const float4*>(w3)[e];
    }
    for (int e = tid; e < R; e += NT) nix[e] = IDX[(size_t)bs0*K + e];
    for (int e = tid; e < BC*C3; e += NT) mbuf[e] = 0;   // int 0 == float 0.0f (relu floor)
    for (int e = tid; e < BC*C1; e += NT){
        int c = e / C1, ch = e - c*C1;
        const float* wr = w1 + ch*67;
        const float* ce = newxyz + (size_t)(bs0 + c)*3;
        Rs[e] = fmaf(wr[2], ce[2], fmaf(wr[1], ce[1], wr[0]*ce[0]));
    }
    __syncthreads();

    // gather + h1 = relu(PQ[nix] - Rs)
    {
        constexpr int C1v = C1/4;
        const float4* PQ4 = reinterpret_cast<const float4*>(PQ + (size_t)b * NP * C1);
        for (int e = tid; e < R*C1v; e += NT){
            int r = e / C1v, q = e - r*C1v;
            float4 v  = PQ4[(size_t)nix[r]*C1v + q];
            float4 rv = *reinterpret_cast<const float4*>(&Rs[(r/K)*C1 + 4*q]);
            v.x = fmaxf(v.x - rv.x, 0.f); v.y = fmaxf(v.y - rv.y, 0.f);
            v.z = fmaxf(v.z - rv.z, 0.f); v.w = fmaxf(v.w - rv.w, 0.f);
            *reinterpret_cast<float4*>(&h1[r*P1 + 4*q]) = v;
        }
    }
    __syncthreads();

    // ---- layer 2: H2[R x C2] = relu(H1 @ W2^T + b2) ----
    {
        constexpr int TR = R/GR2, TC = C2/GC2;
        const int tr = tid / GC2, tc = tid - (tid / GC2)*GC2;
        float2 acc[TR][TC];
#pragma unroll
        for (int i = 0; i < TR; i++)
#pragma unroll
            for (int j = 0; j < TC; j++) acc[i][j] = make_float2(0.f, 0.f);
#pragma unroll 2
        for (int kk = 0; kk < C1; kk += 4){
            float4 a[TR];
#pragma unroll
            for (int i = 0; i < TR; i++)
                a[i] = *reinterpret_cast<const float4*>(&h1[(tr + GR2*i)*P1 + kk]);
#pragma unroll
            for (int j = 0; j < TC; j++){
                float4 w = *reinterpret_cast<const float4*>(&w2s[(tc + GC2*j)*P1 + kk]);
#pragma unroll
                for (int i = 0; i < TR; i++){
                    acc[i][j] = ffma2(f2lo(a[i]), f2lo(w), acc[i][j]);
                    acc[i][j] = ffma2(f2hi(a[i]), f2hi(w), acc[i][j]);
                }
            }
        }
#pragma unroll
        for (int j = 0; j < TC; j++){
            float bb = b2[tc + GC2*j];
#pragma unroll
            for (int i = 0; i < TR; i++)
                h2[(tr + GR2*i)*P2 + tc + GC2*j] = fmaxf(acc[i][j].x + acc[i][j].y + bb, 0.f);
        }
    }
    __syncthreads();

    // ---- layer 3 + fused maxpool over k (per center) ----
    {
        constexpr int TR = R/GR3, TC = C3/GC3;
        const int tr = tid / GC3, tc = tid - (tid / GC3)*GC3;
        float2 acc[TR][TC];
#pragma unroll
        for (int i = 0; i < TR; i++)
#pragma unroll
            for (int j = 0; j < TC; j++) acc[i][j] = make_float2(0.f, 0.f);
#pragma unroll 2
        for (int kk = 0; kk < C2; kk += 4){
            float4 a[TR];
#pragma unroll
            for (int i = 0; i < TR; i++)
                a[i] = *reinterpret_cast<const float4*>(&h2[(tr + GR3*i)*P2 + kk]);
#pragma unroll
            for (int j = 0; j < TC; j++){
                float4 w = *reinterpret_cast<const float4*>(&w3s[(tc + GC3*j)*P2 + kk]);
#pragma unroll
                for (int i = 0; i < TR; i++){
                    acc[i][j] = ffma2(f2lo(a[i]), f2lo(w), acc[i][j]);
                    acc[i][j] = ffma2(f2hi(a[i]), f2hi(w), acc[i][j]);
                }
            }
        }
#pragma unroll
        for (int j = 0; j < TC; j++){
            float bb = b3[tc + GC3*j];
            float vm = -1e30f;
            int prevc = tr / K;
#pragma unroll
            for (int i = 0; i < TR; i++){
                int cen = (tr + GR3*i) / K;
                if (cen != prevc){
                    atomicMax(&mbuf[prevc*C3 + tc + GC3*j], __float_as_int(vm));
                    vm = -1e30f; prevc = cen;
                }
                vm = fmaxf(vm, acc[i][j].x + acc[i][j].y + bb);
            }
            atomicMax(&mbuf[prevc*C3 + tc + GC3*j], __float_as_int(vm));
        }
    }
    __syncthreads();

    for (int e = tid; e < BC*C3; e += NT){
        int c = e / C3, col = e - c*C3;
        out[(size_t)(bs0 + c)*320 + off + col] = __int_as_float(mbuf[e]);
    }
}

// smem sizes (bytes): floats(h1+h2+w2s+w3s+Rs) + ints(nix+mbuf)
template<int BC,int K,int C1,int C2,int C3,int P1,int P2>
constexpr int mlp_smem(){
    return (BC*K*P1 + BC*K*P2 + C2*P1 + C3*P2 + BC*C1)*4 + (BC*K + BC*C3)*4;
}

// ---------------- launch ----------------
extern "C" void kernel_launch(void* const* d_in, const int* in_sizes, int n_in,
                              void* d_out, int out_size)
{
    const float* xyz  = (const float*)d_in[0];
    const float* feat = (const float*)d_in[1];
    const float* W[3][3]; const float* Bi[3][3];
    for (int i = 0; i < 3; i++)
        for (int j = 0; j < 3; j++){
            W[i][j]  = (const float*)d_in[2 + i*6 + j*2];
            Bi[i][j] = (const float*)d_in[3 + i*6 + j*2];
        }
    float* newxyz   = (float*)d_out;                 // (B, S, 3)
    float* feat_out = (float*)d_out + NB*NS*3;       // (B, S, 320)

    // scale0: BC=8,K=16; 256 thr; L2 32x8 (TR4,TC4); L3 32x8 (TR4,TC8)
    constexpr int SM0 = mlp_smem<8,16,32,32,64,36,36>();
    // scale1: BC=4,K=32; 256 thr; L2 16x16 (TR8,TC4); L3 16x16 (TR8,TC8)
    constexpr int SM1 = mlp_smem<4,32,64,64,128,68,68>();
    // scale2: BC=1,K=128; 512 thr; L2 32x16 (TR4,TC6); L3 32x16 (TR4,TC8)
    constexpr int SM2 = mlp_smem<1,128,64,96,128,68,100>();
    constexpr int SMF = 3*NP*4;  // fps: 48KB dynamic — MUST opt-in (R6 failure: missing this)

    cudaFuncSetAttribute((const void*)fps_kernel,
                         cudaFuncAttributeMaxDynamicSharedMemorySize, SMF);
    cudaFuncSetAttribute((const void*)mlp_kernel<0,256,8,16,32,32,64,36,36,32,8,32,8>,
                         cudaFuncAttributeMaxDynamicSharedMemorySize, SM0);
    cudaFuncSetAttribute((const void*)mlp_kernel<1,256,4,32,64,64,128,68,68,16,16,16,16>,
                         cudaFuncAttributeMaxDynamicSharedMemorySize, SM1);
    cudaFuncSetAttribute((const void*)mlp_kernel<2,512,1,128,64,96,128,68,100,32,16,32,16>,
                         cudaFuncAttributeMaxDynamicSharedMemorySize, SM2);

    fps_kernel<<<NB, 1024, SMF>>>(xyz, newxyz);
    pq_kernel<<<NB*NP/32, 160>>>(xyz, feat,
        W[0][0], Bi[0][0], W[1][0], Bi[1][0], W[2][0], Bi[2][0]);
    ball_kernel<<<NB*NS, 128>>>(xyz, newxyz);

    mlp_kernel<0,256,8,16,32,32,64,36,36,32,8,32,8><<<NB*NS/8, 256, SM0>>>(
        W[0][0], W[0][1], Bi[0][1], W[0][2], Bi[0][2], newxyz, feat_out, 0);
    mlp_kernel<1,256,4,32,64,64,128,68,68,16,16,16,16><<<NB*NS/4, 256, SM1>>>(
        W[1][0], W[1][1], Bi[1][1], W[1][2], Bi[1][2], newxyz, feat_out, 64);
    mlp_kernel<2,512,1,128,64,96,128,68,100,32,16,32,16><<<NB*NS, 512, SM2>>>(
        W[2][0], W[2][1], Bi[2][1], W[2][2], Bi[2][2], newxyz, feat_out, 192);
}